// round 14
// baseline (speedup 1.0000x reference)
#include <cuda_runtime.h>
#include <math.h>

// Problem constants
#define NN   50000
#define DD   128
#define MM   800000
#define EE   32
#define KIN  160    // D + E
#define MSGD 128

// Edge kernel tiling: 64 edges/block, 256 threads, per-thread 8 rows x 4 cols
#define TE   64
#define EIS  164    // padded stride for edge-input tile
#define HS   260    // padded stride for hidden tile

// GRU kernel tiling
#define TN   32
#define XS   128
#define GS   384

typedef unsigned long long u64;

// Scratch (allocation-free rule: __device__ globals)
__device__ float g_msgsum[(size_t)NN * DD];
__device__ float g_bufA[(size_t)NN * DD];
__device__ float g_bufB[(size_t)NN * DD];

__device__ __forceinline__ float sigf(float x) { return 1.0f / (1.0f + expf(-x)); }

// ---- packed f32x2 helpers (bit-identical to 2x scalar FFMA) ----
__device__ __forceinline__ u64 pack2(float x) {
    u64 r;
    asm("mov.b64 %0, {%1, %1};" : "=l"(r) : "r"(__float_as_uint(x)));
    return r;
}
__device__ __forceinline__ void ffma2(u64& d, u64 a, u64 b) {
    asm("fma.rn.f32x2 %0, %1, %2, %0;" : "+l"(d) : "l"(a), "l"(b));
}
__device__ __forceinline__ void unpack2(u64 v, float& lo, float& hi) {
    unsigned int a, b;
    asm("mov.b64 {%0, %1}, %2;" : "=r"(a), "=r"(b) : "l"(v));
    lo = __uint_as_float(a); hi = __uint_as_float(b);
}

// ---------------------------------------------------------------------------
__global__ void copy_relu_kernel(const float* __restrict__ src, float* __restrict__ dst,
                                 int n, int do_relu) {
    int i = blockIdx.x * blockDim.x + threadIdx.x;
    if (i < n) {
        float v = src[i];
        dst[i] = do_relu ? fmaxf(v, 0.0f) : v;
    }
}

// ---------------------------------------------------------------------------
// GEMM core: A rows via broadcast LDS.64 k-pairs, W row via one lane-distinct
// LDG.128 per warp per k (cb=lane*4). BOTH operands double-buffered one
// k-pair ahead (software pipeline) so the steady-state loop has no exposed
// LDS/LDG latency. acc[row][2] packed f32x2 over col pairs.
// ---------------------------------------------------------------------------
__device__ __forceinline__ void gemm8(
    const float* __restrict__ As, int astride, int aoff,
    const float* __restrict__ Wp, int kcnt, int cb, int rb,
    u64 (&acc)[8][2])
{
    ulonglong2 wa = *(const ulonglong2*)(Wp + cb);                 // k0 row
    ulonglong2 wb = *(const ulonglong2*)(Wp + MSGD + cb);          // k0+1 row
    float2 aC[8];
    #pragma unroll
    for (int r = 0; r < 8; r++)
        aC[r] = *(const float2*)(As + (rb + r) * astride + aoff);

    #pragma unroll 2
    for (int k0 = 0; k0 < kcnt; k0 += 2) {
        int kn = (k0 + 2 < kcnt) ? (k0 + 2) : 0;
        ulonglong2 na = *(const ulonglong2*)(Wp + kn * MSGD + cb);
        ulonglong2 nb = *(const ulonglong2*)(Wp + (kn + 1) * MSGD + cb);
        float2 aN[8];
        #pragma unroll
        for (int r = 0; r < 8; r++)
            aN[r] = *(const float2*)(As + (rb + r) * astride + aoff + kn);

        #pragma unroll
        for (int r = 0; r < 8; r++) {
            u64 p0 = pack2(aC[r].x);
            u64 p1 = pack2(aC[r].y);
            ffma2(acc[r][0], p0, wa.x);
            ffma2(acc[r][1], p0, wa.y);
            ffma2(acc[r][0], p1, wb.x);
            ffma2(acc[r][1], p1, wb.y);
        }
        #pragma unroll
        for (int r = 0; r < 8; r++) aC[r] = aN[r];
        wa = na; wb = nb;
    }
}

// ---------------------------------------------------------------------------
// Fused edge kernel. 64 edges/block, 256 threads.
// Thread tile: 8 rows (rb = warp*8) x 4 cols (cb = lane*4).
// 108.5KB smem -> 2 blocks/SM = 16 warps (occ 25%).
// ---------------------------------------------------------------------------
__global__ void __launch_bounds__(256, 2)
edge_kernel(const float* __restrict__ state,
            const int*   __restrict__ eidx,
            const float* __restrict__ efeat,
            const float* __restrict__ W1p, const float* __restrict__ b1p,
            const float* __restrict__ W2p, const float* __restrict__ b2p,
            const float* __restrict__ A1p, const float* __restrict__ ab1p,
            const float* __restrict__ A2p, const float* __restrict__ ab2p,
            float* __restrict__ msum)
{
    extern __shared__ float sm[];
    float* s_ei = sm;              // TE * EIS  (reused as gate buffer later)
    float* s_h  = sm + TE * EIS;   // TE * HS
    __shared__ int s_src[TE];
    __shared__ int s_dst[TE];

    const int tid = threadIdx.x;
    const int m0  = blockIdx.x * TE;

    if (tid < TE) {
        s_src[tid] = eidx[m0 + tid];
        s_dst[tid] = eidx[MM + m0 + tid];
    }
    __syncthreads();

    // Gather diff part: 64 edges x 32 float4
    for (int t = tid; t < TE * 32; t += 256) {
        int e = t >> 5, q = t & 31;
        const float4 a = ((const float4*)(state + (size_t)s_src[e] * DD))[q];
        const float4 b = ((const float4*)(state + (size_t)s_dst[e] * DD))[q];
        float4 v; v.x = a.x - b.x; v.y = a.y - b.y; v.z = a.z - b.z; v.w = a.w - b.w;
        *(float4*)(s_ei + e * EIS + q * 4) = v;
    }
    // Edge features: 64 edges x 8 float4
    for (int t = tid; t < TE * 8; t += 256) {
        int e = t >> 3, q = t & 7;
        float4 v = ((const float4*)(efeat + (size_t)(m0 + e) * EE))[q];
        *(float4*)(s_ei + e * EIS + DD + q * 4) = v;
    }
    __syncthreads();

    const int lane = tid & 31;
    const int warp = tid >> 5;
    const int cb   = lane * 4;   // 32 lanes cover 128 cols, one LDG.128/warp
    const int rb   = warp * 8;   // 8 warps cover 64 rows

    // ---- GEMM1: H = relu(EI @ W + b), halves: 0 = msg net (W1), 1 = att net (A1)
    #pragma unroll
    for (int half = 0; half < 2; half++) {
        const float* Wp = half ? A1p : W1p;
        const float* bp = half ? ab1p : b1p;
        u64 acc[8][2];
        #pragma unroll
        for (int r = 0; r < 8; r++) { acc[r][0] = 0ull; acc[r][1] = 0ull; }

        gemm8(s_ei, EIS, 0, Wp, KIN, cb, rb, acc);

        const float4 bias = *(const float4*)(bp + cb);
        #pragma unroll
        for (int r = 0; r < 8; r++) {
            float v0, v1, v2, v3;
            unpack2(acc[r][0], v0, v1);
            unpack2(acc[r][1], v2, v3);
            float4 o;
            o.x = fmaxf(v0 + bias.x, 0.f);
            o.y = fmaxf(v1 + bias.y, 0.f);
            o.z = fmaxf(v2 + bias.z, 0.f);
            o.w = fmaxf(v3 + bias.w, 0.f);
            *(float4*)(s_h + (rb + r) * HS + half * MSGD + cb) = o;
        }
    }
    __syncthreads();
    // s_ei is dead now; reuse as per-thread gate buffer.

    // ---- GEMM2a: att = HA @ A2 + ab2 -> gate = sigmoid, staged in s_ei ----
    {
        u64 acc[8][2];
        #pragma unroll
        for (int r = 0; r < 8; r++) { acc[r][0] = 0ull; acc[r][1] = 0ull; }

        gemm8(s_h, HS, MSGD, A2p, MSGD, cb, rb, acc);

        const float4 ab = *(const float4*)(ab2p + cb);
        #pragma unroll
        for (int r = 0; r < 8; r++) {
            float a0, a1, a2, a3;
            unpack2(acc[r][0], a0, a1);
            unpack2(acc[r][1], a2, a3);
            float4 g;
            g.x = sigf(a0 + ab.x);
            g.y = sigf(a1 + ab.y);
            g.z = sigf(a2 + ab.z);
            g.w = sigf(a3 + ab.w);
            *(float4*)(s_ei + (rb + r) * EIS + cb) = g;
        }
    }

    // ---- GEMM2b: msg = H1 @ W2 + b2; scatter msg*gate into msum ----
    {
        u64 acc[8][2];
        #pragma unroll
        for (int r = 0; r < 8; r++) { acc[r][0] = 0ull; acc[r][1] = 0ull; }

        gemm8(s_h, HS, 0, W2p, MSGD, cb, rb, acc);

        const float4 b2v = *(const float4*)(b2p + cb);
        #pragma unroll
        for (int r = 0; r < 8; r++) {
            float m0v, m1v, m2v, m3v;
            unpack2(acc[r][0], m0v, m1v);
            unpack2(acc[r][1], m2v, m3v);
            float4 g = *(const float4*)(s_ei + (rb + r) * EIS + cb);
            float* dp = msum + (size_t)s_dst[rb + r] * DD + cb;
            atomicAdd(dp + 0, (m0v + b2v.x) * g.x);
            atomicAdd(dp + 1, (m1v + b2v.y) * g.y);
            atomicAdd(dp + 2, (m2v + b2v.z) * g.z);
            atomicAdd(dp + 3, (m3v + b2v.w) * g.w);
        }
    }
}

// ---------------------------------------------------------------------------
// Fused GRU kernel: per 32-node tile, 256 threads, f32x2 + weight prefetch.
// ---------------------------------------------------------------------------
__global__ void __launch_bounds__(256)
gru_kernel(const float* __restrict__ xmsg, const float* __restrict__ hstate,
           const float* __restrict__ Wih, const float* __restrict__ bih,
           const float* __restrict__ Whh, const float* __restrict__ bhh,
           float* __restrict__ out)
{
    extern __shared__ float sm[];
    float* s_x  = sm;                        // TN * XS
    float* s_h  = s_x + TN * XS;             // TN * XS
    float* s_gi = s_h + TN * XS;             // TN * GS
    float* s_gh = s_gi + TN * GS;            // TN * GS

    const int tid = threadIdx.x;
    const int n0  = blockIdx.x * TN;

    for (int t = tid; t < TN * 32; t += 256) {
        int r = t >> 5, q = t & 31;
        int node = n0 + r;
        float4 vx = make_float4(0.f, 0.f, 0.f, 0.f);
        float4 vh = vx;
        if (node < NN) {
            vx = ((const float4*)(xmsg   + (size_t)node * DD))[q];
            vh = ((const float4*)(hstate + (size_t)node * DD))[q];
        }
        *(float4*)(s_x + r * XS + q * 4) = vx;
        *(float4*)(s_h + r * XS + q * 4) = vh;
    }
    __syncthreads();

    const int lane = tid & 31;
    const int wg   = tid >> 5;
    const int rb   = wg * 4;
    const int cb   = lane * 12;

    #pragma unroll
    for (int pass = 0; pass < 2; pass++) {
        const float* xs = pass ? s_h : s_x;
        const float* Wp = pass ? Whh : Wih;
        const float* bp = pass ? bhh : bih;
        float* gout     = pass ? s_gh : s_gi;

        u64 acc[4][6];
        #pragma unroll
        for (int i = 0; i < 4; i++)
            #pragma unroll
            for (int j = 0; j < 6; j++) acc[i][j] = 0ull;

        ulonglong2 w0a = *(const ulonglong2*)(Wp + 0 * 384 + cb);
        ulonglong2 w1a = *(const ulonglong2*)(Wp + 0 * 384 + cb + 4);
        ulonglong2 w2a = *(const ulonglong2*)(Wp + 0 * 384 + cb + 8);
        for (int k = 0; k < DD; k++) {
            int kn = (k + 1 < DD) ? (k + 1) : 0;
            ulonglong2 w0b = *(const ulonglong2*)(Wp + kn * 384 + cb);
            ulonglong2 w1b = *(const ulonglong2*)(Wp + kn * 384 + cb + 4);
            ulonglong2 w2b = *(const ulonglong2*)(Wp + kn * 384 + cb + 8);
            #pragma unroll
            for (int i = 0; i < 4; i++) {
                u64 xv = pack2(xs[(rb + i) * XS + k]);
                ffma2(acc[i][0], xv, w0a.x);
                ffma2(acc[i][1], xv, w0a.y);
                ffma2(acc[i][2], xv, w1a.x);
                ffma2(acc[i][3], xv, w1a.y);
                ffma2(acc[i][4], xv, w2a.x);
                ffma2(acc[i][5], xv, w2a.y);
            }
            w0a = w0b; w1a = w1b; w2a = w2b;
        }
        #pragma unroll
        for (int i = 0; i < 4; i++) {
            #pragma unroll
            for (int j = 0; j < 6; j++) {
                float lo, hi;
                unpack2(acc[i][j], lo, hi);
                gout[(rb + i) * GS + cb + 2 * j]     = lo + bp[cb + 2 * j];
                gout[(rb + i) * GS + cb + 2 * j + 1] = hi + bp[cb + 2 * j + 1];
            }
        }
        __syncthreads();
    }

    for (int t = tid; t < TN * DD; t += 256) {
        int r = t >> 7, j = t & 127;
        int node = n0 + r;
        if (node >= NN) continue;
        float gir = s_gi[r * GS + j];
        float giz = s_gi[r * GS + 128 + j];
        float gin = s_gi[r * GS + 256 + j];
        float ghr = s_gh[r * GS + j];
        float ghz = s_gh[r * GS + 128 + j];
        float ghn = s_gh[r * GS + 256 + j];
        float h   = s_h[r * XS + j];
        float rr  = sigf(gir + ghr);
        float zz  = sigf(giz + ghz);
        float nn  = tanhf(gin + rr * ghn);
        out[(size_t)node * DD + j] = (1.0f - zz) * nn + zz * h;
    }
}

// ---------------------------------------------------------------------------
extern "C" void kernel_launch(void* const* d_in, const int* in_sizes, int n_in,
                              void* d_out, int out_size) {
    const float* node_feat = (const float*)d_in[0];
    const int*   edge_index = (const int*)d_in[1];
    const float* edge_feat = (const float*)d_in[2];
    const float* W1  = (const float*)d_in[3];
    const float* b1  = (const float*)d_in[4];
    const float* W2  = (const float*)d_in[5];
    const float* b2  = (const float*)d_in[6];
    const float* A1  = (const float*)d_in[7];
    const float* ab1 = (const float*)d_in[8];
    const float* A2  = (const float*)d_in[9];
    const float* ab2 = (const float*)d_in[10];
    const float* Wih = (const float*)d_in[11];
    const float* bih = (const float*)d_in[12];
    const float* Whh = (const float*)d_in[13];
    const float* bhh = (const float*)d_in[14];

    float *msum, *bufA, *bufB;
    cudaGetSymbolAddress((void**)&msum, g_msgsum);
    cudaGetSymbolAddress((void**)&bufA, g_bufA);
    cudaGetSymbolAddress((void**)&bufB, g_bufB);

    const int EDGE_SMEM = (TE * EIS + TE * HS) * (int)sizeof(float);         // 108.5 KB
    const int GRU_SMEM  = (2 * TN * XS + 2 * TN * GS) * (int)sizeof(float);  // 128 KB
    cudaFuncSetAttribute(edge_kernel, cudaFuncAttributeMaxDynamicSharedMemorySize, EDGE_SMEM);
    cudaFuncSetAttribute(gru_kernel,  cudaFuncAttributeMaxDynamicSharedMemorySize, GRU_SMEM);

    const int nElems = NN * DD;

    copy_relu_kernel<<<(nElems + 255) / 256, 256>>>(node_feat, bufA, nElems, 0);

    float* cur = bufA;
    float* nxt = bufB;

    for (int step = 0; step < 4; step++) {
        int ii = step >> 1;

        if (step == 2) {
            copy_relu_kernel<<<(nElems + 255) / 256, 256>>>(cur, cur, nElems, 1);
        }

        cudaMemsetAsync(msum, 0, sizeof(float) * (size_t)nElems);

        edge_kernel<<<MM / TE, 256, EDGE_SMEM>>>(
            cur, edge_index, edge_feat,
            W1 + (size_t)ii * KIN * MSGD,  b1  + (size_t)ii * MSGD,
            W2 + (size_t)ii * MSGD * MSGD, b2  + (size_t)ii * MSGD,
            A1 + (size_t)ii * KIN * MSGD,  ab1 + (size_t)ii * MSGD,
            A2 + (size_t)ii * MSGD * MSGD, ab2 + (size_t)ii * MSGD,
            msum);

        float* outp = (step == 3) ? (float*)d_out : nxt;

        gru_kernel<<<(NN + TN - 1) / TN, 256, GRU_SMEM>>>(
            msum, cur,
            Wih + (size_t)ii * MSGD * 384, bih + (size_t)ii * 384,
            Whh + (size_t)ii * DD * 384,   bhh + (size_t)ii * 384,
            outp);

        if (step < 3) { float* t = cur; cur = nxt; nxt = t; }
    }
}

// round 15
// speedup vs baseline: 1.0002x; 1.0002x over previous
#include <cuda_runtime.h>
#include <math.h>

// Problem constants
#define NN   50000
#define DD   128
#define MM   800000
#define EE   32
#define KIN  160    // D + E
#define MSGD 128

// Edge kernel tiling: 64 edges/block, 256 threads, per-thread 8 rows x 4 cols
#define TE   64
#define EIS  164    // padded stride for edge-input tile
#define HS   260    // padded stride for hidden tile

// GRU kernel tiling
#define TN   32
#define XS   128
#define GS   384

typedef unsigned long long u64;

// Scratch (allocation-free rule: __device__ globals)
__device__ float g_msgsum[(size_t)NN * DD];
__device__ float g_bufA[(size_t)NN * DD];
__device__ float g_bufB[(size_t)NN * DD];

__device__ __forceinline__ float sigf(float x) { return 1.0f / (1.0f + expf(-x)); }

// ---- packed f32x2 helpers (bit-identical to 2x scalar FFMA) ----
__device__ __forceinline__ u64 pack2(float x) {
    u64 r;
    asm("mov.b64 %0, {%1, %1};" : "=l"(r) : "r"(__float_as_uint(x)));
    return r;
}
__device__ __forceinline__ void ffma2(u64& d, u64 a, u64 b) {
    asm("fma.rn.f32x2 %0, %1, %2, %0;" : "+l"(d) : "l"(a), "l"(b));
}
__device__ __forceinline__ void unpack2(u64 v, float& lo, float& hi) {
    unsigned int a, b;
    asm("mov.b64 {%0, %1}, %2;" : "=r"(a), "=r"(b) : "l"(v));
    lo = __uint_as_float(a); hi = __uint_as_float(b);
}

// ---------------------------------------------------------------------------
__global__ void copy_relu_kernel(const float* __restrict__ src, float* __restrict__ dst,
                                 int n, int do_relu) {
    int i = blockIdx.x * blockDim.x + threadIdx.x;
    if (i < n) {
        float v = src[i];
        dst[i] = do_relu ? fmaxf(v, 0.0f) : v;
    }
}

// ---------------------------------------------------------------------------
// GEMM core: A rows via broadcast LDS.64 k-pairs, W rows via lane-distinct
// LDG.128 (cb = lane*4). Zero-copy ping-pong software pipeline: the k-loop
// is unrolled by 4 into two phases with two named buffer sets (aA,wA)/(aB,wB)
// so the "advance" is pure register renaming -- no MOV copies.
// Requires kcnt % 4 == 0 (160, 128 both qualify).
// ---------------------------------------------------------------------------
__device__ __forceinline__ void gemm8(
    const float* __restrict__ As, int astride, int aoff,
    const float* __restrict__ Wp, int kcnt, int cb, int rb,
    u64 (&acc)[8][2])
{
    ulonglong2 wA0 = *(const ulonglong2*)(Wp + cb);
    ulonglong2 wA1 = *(const ulonglong2*)(Wp + MSGD + cb);
    float2 aA[8];
    #pragma unroll
    for (int r = 0; r < 8; r++)
        aA[r] = *(const float2*)(As + (rb + r) * astride + aoff);

    for (int k0 = 0; k0 < kcnt; k0 += 4) {
        // ---- phase 1: prefetch k0+2/k0+3 into (aB,wB); compute k0/k0+1 ----
        const int k2 = k0 + 2;
        ulonglong2 wB0 = *(const ulonglong2*)(Wp + k2 * MSGD + cb);
        ulonglong2 wB1 = *(const ulonglong2*)(Wp + (k2 + 1) * MSGD + cb);
        float2 aB[8];
        #pragma unroll
        for (int r = 0; r < 8; r++)
            aB[r] = *(const float2*)(As + (rb + r) * astride + aoff + k2);
        #pragma unroll
        for (int r = 0; r < 8; r++) {
            u64 p0 = pack2(aA[r].x);
            u64 p1 = pack2(aA[r].y);
            ffma2(acc[r][0], p0, wA0.x);
            ffma2(acc[r][1], p0, wA0.y);
            ffma2(acc[r][0], p1, wA1.x);
            ffma2(acc[r][1], p1, wA1.y);
        }
        // ---- phase 2: prefetch k0+4 (wrap->0 dummy) into (aA,wA); compute k0+2/k0+3
        const int k4 = (k0 + 4 < kcnt) ? (k0 + 4) : 0;
        wA0 = *(const ulonglong2*)(Wp + k4 * MSGD + cb);
        wA1 = *(const ulonglong2*)(Wp + (k4 + 1) * MSGD + cb);
        #pragma unroll
        for (int r = 0; r < 8; r++)
            aA[r] = *(const float2*)(As + (rb + r) * astride + aoff + k4);
        #pragma unroll
        for (int r = 0; r < 8; r++) {
            u64 p0 = pack2(aB[r].x);
            u64 p1 = pack2(aB[r].y);
            ffma2(acc[r][0], p0, wB0.x);
            ffma2(acc[r][1], p0, wB0.y);
            ffma2(acc[r][0], p1, wB1.x);
            ffma2(acc[r][1], p1, wB1.y);
        }
    }
}

// ---------------------------------------------------------------------------
// Fused edge kernel. 64 edges/block, 256 threads.
// Thread tile: 8 rows (rb = warp*8) x 4 cols (cb = lane*4).
// 108.5KB smem -> 2 blocks/SM = 16 warps (occ 25%).
// ---------------------------------------------------------------------------
__global__ void __launch_bounds__(256, 2)
edge_kernel(const float* __restrict__ state,
            const int*   __restrict__ eidx,
            const float* __restrict__ efeat,
            const float* __restrict__ W1p, const float* __restrict__ b1p,
            const float* __restrict__ W2p, const float* __restrict__ b2p,
            const float* __restrict__ A1p, const float* __restrict__ ab1p,
            const float* __restrict__ A2p, const float* __restrict__ ab2p,
            float* __restrict__ msum)
{
    extern __shared__ float sm[];
    float* s_ei = sm;              // TE * EIS  (reused as gate buffer later)
    float* s_h  = sm + TE * EIS;   // TE * HS
    __shared__ int s_src[TE];
    __shared__ int s_dst[TE];

    const int tid = threadIdx.x;
    const int m0  = blockIdx.x * TE;

    if (tid < TE) {
        s_src[tid] = eidx[m0 + tid];
        s_dst[tid] = eidx[MM + m0 + tid];
    }
    __syncthreads();

    // Gather diff part: 64 edges x 32 float4
    for (int t = tid; t < TE * 32; t += 256) {
        int e = t >> 5, q = t & 31;
        const float4 a = ((const float4*)(state + (size_t)s_src[e] * DD))[q];
        const float4 b = ((const float4*)(state + (size_t)s_dst[e] * DD))[q];
        float4 v; v.x = a.x - b.x; v.y = a.y - b.y; v.z = a.z - b.z; v.w = a.w - b.w;
        *(float4*)(s_ei + e * EIS + q * 4) = v;
    }
    // Edge features: 64 edges x 8 float4
    for (int t = tid; t < TE * 8; t += 256) {
        int e = t >> 3, q = t & 7;
        float4 v = ((const float4*)(efeat + (size_t)(m0 + e) * EE))[q];
        *(float4*)(s_ei + e * EIS + DD + q * 4) = v;
    }
    __syncthreads();

    const int lane = tid & 31;
    const int warp = tid >> 5;
    const int cb   = lane * 4;   // 32 lanes cover 128 cols, one LDG.128/warp
    const int rb   = warp * 8;   // 8 warps cover 64 rows

    // ---- GEMM1: H = relu(EI @ W + b), halves: 0 = msg net (W1), 1 = att net (A1)
    #pragma unroll
    for (int half = 0; half < 2; half++) {
        const float* Wp = half ? A1p : W1p;
        const float* bp = half ? ab1p : b1p;
        u64 acc[8][2];
        #pragma unroll
        for (int r = 0; r < 8; r++) { acc[r][0] = 0ull; acc[r][1] = 0ull; }

        gemm8(s_ei, EIS, 0, Wp, KIN, cb, rb, acc);

        const float4 bias = *(const float4*)(bp + cb);
        #pragma unroll
        for (int r = 0; r < 8; r++) {
            float v0, v1, v2, v3;
            unpack2(acc[r][0], v0, v1);
            unpack2(acc[r][1], v2, v3);
            float4 o;
            o.x = fmaxf(v0 + bias.x, 0.f);
            o.y = fmaxf(v1 + bias.y, 0.f);
            o.z = fmaxf(v2 + bias.z, 0.f);
            o.w = fmaxf(v3 + bias.w, 0.f);
            *(float4*)(s_h + (rb + r) * HS + half * MSGD + cb) = o;
        }
    }
    __syncthreads();
    // s_ei is dead now; reuse as per-thread gate buffer.

    // ---- GEMM2a: att = HA @ A2 + ab2 -> gate = sigmoid, staged in s_ei ----
    {
        u64 acc[8][2];
        #pragma unroll
        for (int r = 0; r < 8; r++) { acc[r][0] = 0ull; acc[r][1] = 0ull; }

        gemm8(s_h, HS, MSGD, A2p, MSGD, cb, rb, acc);

        const float4 ab = *(const float4*)(ab2p + cb);
        #pragma unroll
        for (int r = 0; r < 8; r++) {
            float a0, a1, a2, a3;
            unpack2(acc[r][0], a0, a1);
            unpack2(acc[r][1], a2, a3);
            float4 g;
            g.x = sigf(a0 + ab.x);
            g.y = sigf(a1 + ab.y);
            g.z = sigf(a2 + ab.z);
            g.w = sigf(a3 + ab.w);
            *(float4*)(s_ei + (rb + r) * EIS + cb) = g;
        }
    }

    // ---- GEMM2b: msg = H1 @ W2 + b2; scatter msg*gate into msum ----
    {
        u64 acc[8][2];
        #pragma unroll
        for (int r = 0; r < 8; r++) { acc[r][0] = 0ull; acc[r][1] = 0ull; }

        gemm8(s_h, HS, 0, W2p, MSGD, cb, rb, acc);

        const float4 b2v = *(const float4*)(b2p + cb);
        #pragma unroll
        for (int r = 0; r < 8; r++) {
            float m0v, m1v, m2v, m3v;
            unpack2(acc[r][0], m0v, m1v);
            unpack2(acc[r][1], m2v, m3v);
            float4 g = *(const float4*)(s_ei + (rb + r) * EIS + cb);
            float* dp = msum + (size_t)s_dst[rb + r] * DD + cb;
            atomicAdd(dp + 0, (m0v + b2v.x) * g.x);
            atomicAdd(dp + 1, (m1v + b2v.y) * g.y);
            atomicAdd(dp + 2, (m2v + b2v.z) * g.z);
            atomicAdd(dp + 3, (m3v + b2v.w) * g.w);
        }
    }
}

// ---------------------------------------------------------------------------
// Fused GRU kernel: per 32-node tile, 256 threads, f32x2 + weight prefetch.
// ---------------------------------------------------------------------------
__global__ void __launch_bounds__(256)
gru_kernel(const float* __restrict__ xmsg, const float* __restrict__ hstate,
           const float* __restrict__ Wih, const float* __restrict__ bih,
           const float* __restrict__ Whh, const float* __restrict__ bhh,
           float* __restrict__ out)
{
    extern __shared__ float sm[];
    float* s_x  = sm;                        // TN * XS
    float* s_h  = s_x + TN * XS;             // TN * XS
    float* s_gi = s_h + TN * XS;             // TN * GS
    float* s_gh = s_gi + TN * GS;            // TN * GS

    const int tid = threadIdx.x;
    const int n0  = blockIdx.x * TN;

    for (int t = tid; t < TN * 32; t += 256) {
        int r = t >> 5, q = t & 31;
        int node = n0 + r;
        float4 vx = make_float4(0.f, 0.f, 0.f, 0.f);
        float4 vh = vx;
        if (node < NN) {
            vx = ((const float4*)(xmsg   + (size_t)node * DD))[q];
            vh = ((const float4*)(hstate + (size_t)node * DD))[q];
        }
        *(float4*)(s_x + r * XS + q * 4) = vx;
        *(float4*)(s_h + r * XS + q * 4) = vh;
    }
    __syncthreads();

    const int lane = tid & 31;
    const int wg   = tid >> 5;
    const int rb   = wg * 4;
    const int cb   = lane * 12;

    #pragma unroll
    for (int pass = 0; pass < 2; pass++) {
        const float* xs = pass ? s_h : s_x;
        const float* Wp = pass ? Whh : Wih;
        const float* bp = pass ? bhh : bih;
        float* gout     = pass ? s_gh : s_gi;

        u64 acc[4][6];
        #pragma unroll
        for (int i = 0; i < 4; i++)
            #pragma unroll
            for (int j = 0; j < 6; j++) acc[i][j] = 0ull;

        ulonglong2 w0a = *(const ulonglong2*)(Wp + 0 * 384 + cb);
        ulonglong2 w1a = *(const ulonglong2*)(Wp + 0 * 384 + cb + 4);
        ulonglong2 w2a = *(const ulonglong2*)(Wp + 0 * 384 + cb + 8);
        for (int k = 0; k < DD; k++) {
            int kn = (k + 1 < DD) ? (k + 1) : 0;
            ulonglong2 w0b = *(const ulonglong2*)(Wp + kn * 384 + cb);
            ulonglong2 w1b = *(const ulonglong2*)(Wp + kn * 384 + cb + 4);
            ulonglong2 w2b = *(const ulonglong2*)(Wp + kn * 384 + cb + 8);
            #pragma unroll
            for (int i = 0; i < 4; i++) {
                u64 xv = pack2(xs[(rb + i) * XS + k]);
                ffma2(acc[i][0], xv, w0a.x);
                ffma2(acc[i][1], xv, w0a.y);
                ffma2(acc[i][2], xv, w1a.x);
                ffma2(acc[i][3], xv, w1a.y);
                ffma2(acc[i][4], xv, w2a.x);
                ffma2(acc[i][5], xv, w2a.y);
            }
            w0a = w0b; w1a = w1b; w2a = w2b;
        }
        #pragma unroll
        for (int i = 0; i < 4; i++) {
            #pragma unroll
            for (int j = 0; j < 6; j++) {
                float lo, hi;
                unpack2(acc[i][j], lo, hi);
                gout[(rb + i) * GS + cb + 2 * j]     = lo + bp[cb + 2 * j];
                gout[(rb + i) * GS + cb + 2 * j + 1] = hi + bp[cb + 2 * j + 1];
            }
        }
        __syncthreads();
    }

    for (int t = tid; t < TN * DD; t += 256) {
        int r = t >> 7, j = t & 127;
        int node = n0 + r;
        if (node >= NN) continue;
        float gir = s_gi[r * GS + j];
        float giz = s_gi[r * GS + 128 + j];
        float gin = s_gi[r * GS + 256 + j];
        float ghr = s_gh[r * GS + j];
        float ghz = s_gh[r * GS + 128 + j];
        float ghn = s_gh[r * GS + 256 + j];
        float h   = s_h[r * XS + j];
        float rr  = sigf(gir + ghr);
        float zz  = sigf(giz + ghz);
        float nn  = tanhf(gin + rr * ghn);
        out[(size_t)node * DD + j] = (1.0f - zz) * nn + zz * h;
    }
}

// ---------------------------------------------------------------------------
extern "C" void kernel_launch(void* const* d_in, const int* in_sizes, int n_in,
                              void* d_out, int out_size) {
    const float* node_feat = (const float*)d_in[0];
    const int*   edge_index = (const int*)d_in[1];
    const float* edge_feat = (const float*)d_in[2];
    const float* W1  = (const float*)d_in[3];
    const float* b1  = (const float*)d_in[4];
    const float* W2  = (const float*)d_in[5];
    const float* b2  = (const float*)d_in[6];
    const float* A1  = (const float*)d_in[7];
    const float* ab1 = (const float*)d_in[8];
    const float* A2  = (const float*)d_in[9];
    const float* ab2 = (const float*)d_in[10];
    const float* Wih = (const float*)d_in[11];
    const float* bih = (const float*)d_in[12];
    const float* Whh = (const float*)d_in[13];
    const float* bhh = (const float*)d_in[14];

    float *msum, *bufA, *bufB;
    cudaGetSymbolAddress((void**)&msum, g_msgsum);
    cudaGetSymbolAddress((void**)&bufA, g_bufA);
    cudaGetSymbolAddress((void**)&bufB, g_bufB);

    const int EDGE_SMEM = (TE * EIS + TE * HS) * (int)sizeof(float);         // 108.5 KB
    const int GRU_SMEM  = (2 * TN * XS + 2 * TN * GS) * (int)sizeof(float);  // 128 KB
    cudaFuncSetAttribute(edge_kernel, cudaFuncAttributeMaxDynamicSharedMemorySize, EDGE_SMEM);
    cudaFuncSetAttribute(gru_kernel,  cudaFuncAttributeMaxDynamicSharedMemorySize, GRU_SMEM);

    const int nElems = NN * DD;

    copy_relu_kernel<<<(nElems + 255) / 256, 256>>>(node_feat, bufA, nElems, 0);

    float* cur = bufA;
    float* nxt = bufB;

    for (int step = 0; step < 4; step++) {
        int ii = step >> 1;

        if (step == 2) {
            copy_relu_kernel<<<(nElems + 255) / 256, 256>>>(cur, cur, nElems, 1);
        }

        cudaMemsetAsync(msum, 0, sizeof(float) * (size_t)nElems);

        edge_kernel<<<MM / TE, 256, EDGE_SMEM>>>(
            cur, edge_index, edge_feat,
            W1 + (size_t)ii * KIN * MSGD,  b1  + (size_t)ii * MSGD,
            W2 + (size_t)ii * MSGD * MSGD, b2  + (size_t)ii * MSGD,
            A1 + (size_t)ii * KIN * MSGD,  ab1 + (size_t)ii * MSGD,
            A2 + (size_t)ii * MSGD * MSGD, ab2 + (size_t)ii * MSGD,
            msum);

        float* outp = (step == 3) ? (float*)d_out : nxt;

        gru_kernel<<<(NN + TN - 1) / TN, 256, GRU_SMEM>>>(
            msum, cur,
            Wih + (size_t)ii * MSGD * 384, bih + (size_t)ii * 384,
            Whh + (size_t)ii * DD * 384,   bhh + (size_t)ii * 384,
            outp);

        if (step < 3) { float* t = cur; cur = nxt; nxt = t; }
    }
}

// round 16
// speedup vs baseline: 1.4402x; 1.4399x over previous
#include <cuda_runtime.h>
#include <math.h>

// Problem constants
#define NN   50000
#define DD   128
#define MM   800000
#define EE   32
#define KIN  160    // D + E
#define MSGD 128

// Edge kernel tiling: 64 edges/block, 256 threads, per-thread 8 rows x 4 cols
#define TE   64
#define EFS  36     // efeat tile stride (32 + pad)
#define HS   260    // hidden tile stride (256 + pad)
#define SG   132    // gate tile stride (128 + pad)

// nodeproj tiling
#define NPS  132

// GRU kernel tiling
#define TN   32
#define XS   128
#define GS   384

typedef unsigned long long u64;

// Scratch (allocation-free rule: __device__ globals)
__device__ float g_msgsum[(size_t)NN * DD];
__device__ float g_bufA[(size_t)NN * DD];
__device__ float g_bufB[(size_t)NN * DD];
__device__ float g_npW[(size_t)NN * DD];   // state @ W1[0:128]
__device__ float g_npA[(size_t)NN * DD];   // state @ A1[0:128]

__device__ __forceinline__ float sigf(float x) { return 1.0f / (1.0f + expf(-x)); }

// ---- packed f32x2 helpers (bit-identical to 2x scalar FFMA) ----
__device__ __forceinline__ u64 pack2(float x) {
    u64 r;
    asm("mov.b64 %0, {%1, %1};" : "=l"(r) : "r"(__float_as_uint(x)));
    return r;
}
__device__ __forceinline__ void ffma2(u64& d, u64 a, u64 b) {
    asm("fma.rn.f32x2 %0, %1, %2, %0;" : "+l"(d) : "l"(a), "l"(b));
}
__device__ __forceinline__ void unpack2(u64 v, float& lo, float& hi) {
    unsigned int a, b;
    asm("mov.b64 {%0, %1}, %2;" : "=r"(a), "=r"(b) : "l"(v));
    lo = __uint_as_float(a); hi = __uint_as_float(b);
}

// ---------------------------------------------------------------------------
__global__ void copy_relu_kernel(const float* __restrict__ src, float* __restrict__ dst,
                                 int n, int do_relu) {
    int i = blockIdx.x * blockDim.x + threadIdx.x;
    if (i < n) {
        float v = src[i];
        dst[i] = do_relu ? fmaxf(v, 0.0f) : v;
    }
}

// ---------------------------------------------------------------------------
// GEMM core (R13 winner, unchanged): A rows via broadcast LDS.64 k-pairs,
// W row via one lane-distinct LDG.128 per warp per k (cb=lane*4),
// k-pair W prefetch. acc[row][2] packed f32x2 over col pairs.
// ---------------------------------------------------------------------------
__device__ __forceinline__ void gemm8(
    const float* __restrict__ As, int astride, int aoff,
    const float* __restrict__ Wp, int kcnt, int cb, int rb,
    u64 (&acc)[8][2])
{
    ulonglong2 wa = *(const ulonglong2*)(Wp + cb);
    ulonglong2 wb = *(const ulonglong2*)(Wp + MSGD + cb);
    for (int k0 = 0; k0 < kcnt; k0 += 2) {
        int kn = (k0 + 2 < kcnt) ? (k0 + 2) : 0;
        ulonglong2 na = *(const ulonglong2*)(Wp + kn * MSGD + cb);
        ulonglong2 nb = *(const ulonglong2*)(Wp + (kn + 1) * MSGD + cb);
        #pragma unroll
        for (int r = 0; r < 8; r++) {
            float2 a2 = *(const float2*)(As + (rb + r) * astride + aoff + k0);
            u64 p0 = pack2(a2.x);
            u64 p1 = pack2(a2.y);
            ffma2(acc[r][0], p0, wa.x);
            ffma2(acc[r][1], p0, wa.y);
            ffma2(acc[r][0], p1, wb.x);
            ffma2(acc[r][1], p1, wb.y);
        }
        wa = na; wb = nb;
    }
}

// ---------------------------------------------------------------------------
// Node projection: npW = state @ W1[0:128], npA = state @ A1[0:128].
// 64 nodes/block, 256 threads, same gemm8 tiling.
// ---------------------------------------------------------------------------
__global__ void __launch_bounds__(256)
nodeproj_kernel(const float* __restrict__ state,
                const float* __restrict__ W1p, const float* __restrict__ A1p,
                float* __restrict__ npW, float* __restrict__ npA)
{
    __shared__ float s_s[64 * NPS];
    const int tid = threadIdx.x;
    const int n0  = blockIdx.x * 64;

    for (int t = tid; t < 64 * 32; t += 256) {
        int r = t >> 5, q = t & 31;
        int node = n0 + r;
        float4 v = make_float4(0.f, 0.f, 0.f, 0.f);
        if (node < NN) v = ((const float4*)(state + (size_t)node * DD))[q];
        *(float4*)(s_s + r * NPS + q * 4) = v;
    }
    __syncthreads();

    const int lane = tid & 31;
    const int warp = tid >> 5;
    const int cb   = lane * 4;
    const int rb   = warp * 8;

    #pragma unroll
    for (int half = 0; half < 2; half++) {
        const float* Wp = half ? A1p : W1p;
        float* outp     = half ? npA : npW;
        u64 acc[8][2];
        #pragma unroll
        for (int r = 0; r < 8; r++) { acc[r][0] = 0ull; acc[r][1] = 0ull; }

        gemm8(s_s, NPS, 0, Wp, DD, cb, rb, acc);

        #pragma unroll
        for (int r = 0; r < 8; r++) {
            int node = n0 + rb + r;
            if (node >= NN) continue;
            float v0, v1, v2, v3;
            unpack2(acc[r][0], v0, v1);
            unpack2(acc[r][1], v2, v3);
            float4 o; o.x = v0; o.y = v1; o.z = v2; o.w = v3;
            *(float4*)(outp + (size_t)node * DD + cb) = o;
        }
    }
}

// ---------------------------------------------------------------------------
// Fused edge kernel (linear-GEMM1 decomposition).
// h1 = relu(npW[src]-npW[dst] + efeat@W1E + b1)   (W net; A net likewise)
// then gates = sigmoid(hA@A2+ab2), msg = (h1@W2+b2)*gates -> atomic scatter.
// 64 edges/block, 256 threads, 8 rows x 4 cols per thread.
// smem ~107KB -> 2 blocks/SM (16 warps).
// ---------------------------------------------------------------------------
__global__ void __launch_bounds__(256, 2)
edge_kernel(const float* __restrict__ npW,
            const float* __restrict__ npA,
            const int*   __restrict__ eidx,
            const float* __restrict__ efeat,
            const float* __restrict__ W1Ep, const float* __restrict__ b1p,
            const float* __restrict__ W2p,  const float* __restrict__ b2p,
            const float* __restrict__ A1Ep, const float* __restrict__ ab1p,
            const float* __restrict__ A2p,  const float* __restrict__ ab2p,
            float* __restrict__ msum)
{
    extern __shared__ float sm[];
    float* s_ef = sm;                      // TE * EFS
    float* s_h  = sm + TE * EFS;           // TE * HS  (W half [0:128), A half [128:256))
    float* s_g  = s_h + TE * HS;           // TE * SG  (gates)
    __shared__ int s_src[TE];
    __shared__ int s_dst[TE];

    const int tid = threadIdx.x;
    const int m0  = blockIdx.x * TE;

    if (tid < TE) {
        s_src[tid] = eidx[m0 + tid];
        s_dst[tid] = eidx[MM + m0 + tid];
    }
    __syncthreads();

    // Gather projected node diffs: 64 edges x 64 float4 (32 npW + 32 npA)
    for (int t = tid; t < TE * 64; t += 256) {
        int e = t >> 6, q = t & 63;
        int s = s_src[e], d = s_dst[e];
        float4 va, vb;
        float* dst;
        if (q < 32) {
            va = ((const float4*)(npW + (size_t)s * DD))[q];
            vb = ((const float4*)(npW + (size_t)d * DD))[q];
            dst = s_h + e * HS + q * 4;
        } else {
            va = ((const float4*)(npA + (size_t)s * DD))[q - 32];
            vb = ((const float4*)(npA + (size_t)d * DD))[q - 32];
            dst = s_h + e * HS + 128 + (q - 32) * 4;
        }
        float4 v; v.x = va.x - vb.x; v.y = va.y - vb.y; v.z = va.z - vb.z; v.w = va.w - vb.w;
        *(float4*)dst = v;
    }
    // Edge features: 64 edges x 8 float4
    for (int t = tid; t < TE * 8; t += 256) {
        int e = t >> 3, q = t & 7;
        float4 v = ((const float4*)(efeat + (size_t)(m0 + e) * EE))[q];
        *(float4*)(s_ef + e * EFS + q * 4) = v;
    }
    __syncthreads();

    const int lane = tid & 31;
    const int warp = tid >> 5;
    const int cb   = lane * 4;   // 32 lanes cover 128 cols, one LDG.128/warp
    const int rb   = warp * 8;   // 8 warps cover 64 rows

    // ---- efeat GEMM (kcnt=32) + diff + bias -> relu -> s_h, per net ----
    #pragma unroll
    for (int half = 0; half < 2; half++) {
        const float* Wp = half ? A1Ep : W1Ep;
        const float* bp = half ? ab1p : b1p;
        u64 acc[8][2];
        #pragma unroll
        for (int r = 0; r < 8; r++) { acc[r][0] = 0ull; acc[r][1] = 0ull; }

        gemm8(s_ef, EFS, 0, Wp, EE, cb, rb, acc);

        const float4 bias = *(const float4*)(bp + cb);
        #pragma unroll
        for (int r = 0; r < 8; r++) {
            float* hp = s_h + (rb + r) * HS + half * MSGD + cb;
            float4 dv = *(const float4*)hp;
            float v0, v1, v2, v3;
            unpack2(acc[r][0], v0, v1);
            unpack2(acc[r][1], v2, v3);
            float4 o;
            o.x = fmaxf(v0 + dv.x + bias.x, 0.f);
            o.y = fmaxf(v1 + dv.y + bias.y, 0.f);
            o.z = fmaxf(v2 + dv.z + bias.z, 0.f);
            o.w = fmaxf(v3 + dv.w + bias.w, 0.f);
            *(float4*)hp = o;
        }
    }
    __syncthreads();

    // ---- GEMM2a: att = HA @ A2 + ab2 -> gate = sigmoid, staged in s_g ----
    {
        u64 acc[8][2];
        #pragma unroll
        for (int r = 0; r < 8; r++) { acc[r][0] = 0ull; acc[r][1] = 0ull; }

        gemm8(s_h, HS, MSGD, A2p, MSGD, cb, rb, acc);

        const float4 ab = *(const float4*)(ab2p + cb);
        #pragma unroll
        for (int r = 0; r < 8; r++) {
            float a0, a1, a2, a3;
            unpack2(acc[r][0], a0, a1);
            unpack2(acc[r][1], a2, a3);
            float4 g;
            g.x = sigf(a0 + ab.x);
            g.y = sigf(a1 + ab.y);
            g.z = sigf(a2 + ab.z);
            g.w = sigf(a3 + ab.w);
            *(float4*)(s_g + (rb + r) * SG + cb) = g;
        }
    }

    // ---- GEMM2b: msg = H1 @ W2 + b2; scatter msg*gate into msum ----
    {
        u64 acc[8][2];
        #pragma unroll
        for (int r = 0; r < 8; r++) { acc[r][0] = 0ull; acc[r][1] = 0ull; }

        gemm8(s_h, HS, 0, W2p, MSGD, cb, rb, acc);

        const float4 b2v = *(const float4*)(b2p + cb);
        #pragma unroll
        for (int r = 0; r < 8; r++) {
            float m0v, m1v, m2v, m3v;
            unpack2(acc[r][0], m0v, m1v);
            unpack2(acc[r][1], m2v, m3v);
            float4 g = *(const float4*)(s_g + (rb + r) * SG + cb);
            float* dp = msum + (size_t)s_dst[rb + r] * DD + cb;
            atomicAdd(dp + 0, (m0v + b2v.x) * g.x);
            atomicAdd(dp + 1, (m1v + b2v.y) * g.y);
            atomicAdd(dp + 2, (m2v + b2v.z) * g.z);
            atomicAdd(dp + 3, (m3v + b2v.w) * g.w);
        }
    }
}

// ---------------------------------------------------------------------------
// Fused GRU kernel: per 32-node tile, 256 threads, f32x2 + weight prefetch.
// ---------------------------------------------------------------------------
__global__ void __launch_bounds__(256)
gru_kernel(const float* __restrict__ xmsg, const float* __restrict__ hstate,
           const float* __restrict__ Wih, const float* __restrict__ bih,
           const float* __restrict__ Whh, const float* __restrict__ bhh,
           float* __restrict__ out)
{
    extern __shared__ float sm[];
    float* s_x  = sm;                        // TN * XS
    float* s_h  = s_x + TN * XS;             // TN * XS
    float* s_gi = s_h + TN * XS;             // TN * GS
    float* s_gh = s_gi + TN * GS;            // TN * GS

    const int tid = threadIdx.x;
    const int n0  = blockIdx.x * TN;

    for (int t = tid; t < TN * 32; t += 256) {
        int r = t >> 5, q = t & 31;
        int node = n0 + r;
        float4 vx = make_float4(0.f, 0.f, 0.f, 0.f);
        float4 vh = vx;
        if (node < NN) {
            vx = ((const float4*)(xmsg   + (size_t)node * DD))[q];
            vh = ((const float4*)(hstate + (size_t)node * DD))[q];
        }
        *(float4*)(s_x + r * XS + q * 4) = vx;
        *(float4*)(s_h + r * XS + q * 4) = vh;
    }
    __syncthreads();

    const int lane = tid & 31;
    const int wg   = tid >> 5;
    const int rb   = wg * 4;
    const int cb   = lane * 12;

    #pragma unroll
    for (int pass = 0; pass < 2; pass++) {
        const float* xs = pass ? s_h : s_x;
        const float* Wp = pass ? Whh : Wih;
        const float* bp = pass ? bhh : bih;
        float* gout     = pass ? s_gh : s_gi;

        u64 acc[4][6];
        #pragma unroll
        for (int i = 0; i < 4; i++)
            #pragma unroll
            for (int j = 0; j < 6; j++) acc[i][j] = 0ull;

        ulonglong2 w0a = *(const ulonglong2*)(Wp + 0 * 384 + cb);
        ulonglong2 w1a = *(const ulonglong2*)(Wp + 0 * 384 + cb + 4);
        ulonglong2 w2a = *(const ulonglong2*)(Wp + 0 * 384 + cb + 8);
        for (int k = 0; k < DD; k++) {
            int kn = (k + 1 < DD) ? (k + 1) : 0;
            ulonglong2 w0b = *(const ulonglong2*)(Wp + kn * 384 + cb);
            ulonglong2 w1b = *(const ulonglong2*)(Wp + kn * 384 + cb + 4);
            ulonglong2 w2b = *(const ulonglong2*)(Wp + kn * 384 + cb + 8);
            #pragma unroll
            for (int i = 0; i < 4; i++) {
                u64 xv = pack2(xs[(rb + i) * XS + k]);
                ffma2(acc[i][0], xv, w0a.x);
                ffma2(acc[i][1], xv, w0a.y);
                ffma2(acc[i][2], xv, w1a.x);
                ffma2(acc[i][3], xv, w1a.y);
                ffma2(acc[i][4], xv, w2a.x);
                ffma2(acc[i][5], xv, w2a.y);
            }
            w0a = w0b; w1a = w1b; w2a = w2b;
        }
        #pragma unroll
        for (int i = 0; i < 4; i++) {
            #pragma unroll
            for (int j = 0; j < 6; j++) {
                float lo, hi;
                unpack2(acc[i][j], lo, hi);
                gout[(rb + i) * GS + cb + 2 * j]     = lo + bp[cb + 2 * j];
                gout[(rb + i) * GS + cb + 2 * j + 1] = hi + bp[cb + 2 * j + 1];
            }
        }
        __syncthreads();
    }

    for (int t = tid; t < TN * DD; t += 256) {
        int r = t >> 7, j = t & 127;
        int node = n0 + r;
        if (node >= NN) continue;
        float gir = s_gi[r * GS + j];
        float giz = s_gi[r * GS + 128 + j];
        float gin = s_gi[r * GS + 256 + j];
        float ghr = s_gh[r * GS + j];
        float ghz = s_gh[r * GS + 128 + j];
        float ghn = s_gh[r * GS + 256 + j];
        float h   = s_h[r * XS + j];
        float rr  = sigf(gir + ghr);
        float zz  = sigf(giz + ghz);
        float nn  = tanhf(gin + rr * ghn);
        out[(size_t)node * DD + j] = (1.0f - zz) * nn + zz * h;
    }
}

// ---------------------------------------------------------------------------
extern "C" void kernel_launch(void* const* d_in, const int* in_sizes, int n_in,
                              void* d_out, int out_size) {
    const float* node_feat = (const float*)d_in[0];
    const int*   edge_index = (const int*)d_in[1];
    const float* edge_feat = (const float*)d_in[2];
    const float* W1  = (const float*)d_in[3];
    const float* b1  = (const float*)d_in[4];
    const float* W2  = (const float*)d_in[5];
    const float* b2  = (const float*)d_in[6];
    const float* A1  = (const float*)d_in[7];
    const float* ab1 = (const float*)d_in[8];
    const float* A2  = (const float*)d_in[9];
    const float* ab2 = (const float*)d_in[10];
    const float* Wih = (const float*)d_in[11];
    const float* bih = (const float*)d_in[12];
    const float* Whh = (const float*)d_in[13];
    const float* bhh = (const float*)d_in[14];

    float *msum, *bufA, *bufB, *npW, *npA;
    cudaGetSymbolAddress((void**)&msum, g_msgsum);
    cudaGetSymbolAddress((void**)&bufA, g_bufA);
    cudaGetSymbolAddress((void**)&bufB, g_bufB);
    cudaGetSymbolAddress((void**)&npW, g_npW);
    cudaGetSymbolAddress((void**)&npA, g_npA);

    const int EDGE_SMEM = TE * (EFS + HS + SG) * (int)sizeof(float);         // ~107 KB
    const int GRU_SMEM  = (2 * TN * XS + 2 * TN * GS) * (int)sizeof(float);  // 128 KB
    cudaFuncSetAttribute(edge_kernel, cudaFuncAttributeMaxDynamicSharedMemorySize, EDGE_SMEM);
    cudaFuncSetAttribute(gru_kernel,  cudaFuncAttributeMaxDynamicSharedMemorySize, GRU_SMEM);

    const int nElems = NN * DD;

    copy_relu_kernel<<<(nElems + 255) / 256, 256>>>(node_feat, bufA, nElems, 0);

    float* cur = bufA;
    float* nxt = bufB;

    for (int step = 0; step < 4; step++) {
        int ii = step >> 1;

        if (step == 2) {
            copy_relu_kernel<<<(nElems + 255) / 256, 256>>>(cur, cur, nElems, 1);
        }

        cudaMemsetAsync(msum, 0, sizeof(float) * (size_t)nElems);

        const float* W1p = W1 + (size_t)ii * KIN * MSGD;
        const float* A1p = A1 + (size_t)ii * KIN * MSGD;

        nodeproj_kernel<<<(NN + 63) / 64, 256>>>(cur, W1p, A1p, npW, npA);

        edge_kernel<<<MM / TE, 256, EDGE_SMEM>>>(
            npW, npA, edge_index, edge_feat,
            W1p + (size_t)DD * MSGD,  b1  + (size_t)ii * MSGD,
            W2 + (size_t)ii * MSGD * MSGD, b2  + (size_t)ii * MSGD,
            A1p + (size_t)DD * MSGD,  ab1 + (size_t)ii * MSGD,
            A2 + (size_t)ii * MSGD * MSGD, ab2 + (size_t)ii * MSGD,
            msum);

        float* outp = (step == 3) ? (float*)d_out : nxt;

        gru_kernel<<<(NN + TN - 1) / TN, 256, GRU_SMEM>>>(
            msum, cur,
            Wih + (size_t)ii * MSGD * 384, bih + (size_t)ii * 384,
            Whh + (size_t)ii * DD * 384,   bhh + (size_t)ii * 384,
            outp);

        if (step < 3) { float* t = cur; cur = nxt; nxt = t; }
    }
}